// round 3
// baseline (speedup 1.0000x reference)
#include <cuda_runtime.h>
#include <cuda_bf16.h>
#include <math.h>

// Problem constants
#define S_LEN 2048
#define D_MODEL 2048
#define HEADS 32
#define HEAD_DIM 64
#define NKV 8
#define D_Q (HEADS * HEAD_DIM)      // 2048
#define D_KV (NKV * HEAD_DIM)       // 512

// Scratch (allocation-free rule: __device__ globals)
__device__ float g_q[S_LEN * D_Q];     // 16 MB
__device__ float g_k[S_LEN * D_KV];    // 4 MB
__device__ float g_v[S_LEN * D_KV];    // 4 MB
__device__ float g_ao[S_LEN * D_Q];    // 16 MB

// ---------------------------------------------------------------------------
// Generic SGEMM: C[M,N] = A[M,K] @ B[K,N] (+ bias[N])
// BM=64, BN=64, BK=16, 256 threads, 4x4 microtile per thread.
// Assumes M%64==0, N%64==0, K%16==0 (true for all shapes here).
// ---------------------------------------------------------------------------
__global__ __launch_bounds__(256) void sgemm_kernel(
    const float* __restrict__ A, const float* __restrict__ B,
    float* __restrict__ C, const float* __restrict__ bias,
    int M, int N, int K)
{
    __shared__ float As[64][17];   // padded to dodge bank conflicts
    __shared__ float Bs[16][64];

    const int tid = threadIdx.x;
    const int tx = tid & 15;       // 0..15 -> column group
    const int ty = tid >> 4;       // 0..15 -> row group
    const int m0 = blockIdx.y * 64;
    const int n0 = blockIdx.x * 64;

    // load mappings (float4 per thread)
    const int la_r = tid >> 2;           // 0..63
    const int la_c = (tid & 3) * 4;      // 0,4,8,12
    const int lb_r = tid >> 4;           // 0..15
    const int lb_c = (tid & 15) * 4;     // 0..60

    float acc[4][4] = {};

    for (int k0 = 0; k0 < K; k0 += 16) {
        float4 a4 = *reinterpret_cast<const float4*>(A + (size_t)(m0 + la_r) * K + k0 + la_c);
        As[la_r][la_c + 0] = a4.x;
        As[la_r][la_c + 1] = a4.y;
        As[la_r][la_c + 2] = a4.z;
        As[la_r][la_c + 3] = a4.w;
        float4 b4 = *reinterpret_cast<const float4*>(B + (size_t)(k0 + lb_r) * N + n0 + lb_c);
        *reinterpret_cast<float4*>(&Bs[lb_r][lb_c]) = b4;
        __syncthreads();

        #pragma unroll
        for (int kk = 0; kk < 16; kk++) {
            float ra[4], rb[4];
            #pragma unroll
            for (int i = 0; i < 4; i++) ra[i] = As[ty * 4 + i][kk];
            float4 b = *reinterpret_cast<const float4*>(&Bs[kk][tx * 4]);
            rb[0] = b.x; rb[1] = b.y; rb[2] = b.z; rb[3] = b.w;
            #pragma unroll
            for (int i = 0; i < 4; i++)
                #pragma unroll
                for (int j = 0; j < 4; j++)
                    acc[i][j] = fmaf(ra[i], rb[j], acc[i][j]);
        }
        __syncthreads();
    }

    #pragma unroll
    for (int i = 0; i < 4; i++) {
        const int m = m0 + ty * 4 + i;
        #pragma unroll
        for (int j = 0; j < 4; j++) {
            const int n = n0 + tx * 4 + j;
            float v = acc[i][j];
            if (bias) v += bias[n];
            C[(size_t)m * N + n] = v;
        }
    }
}

// ---------------------------------------------------------------------------
// Fused per-head RMSNorm + RoPE, in place.
// grid = (S, nheads), block = 64 threads (one per head dim).
// data layout: [S, nheads*64], row stride = rowstride.
// ---------------------------------------------------------------------------
__global__ __launch_bounds__(64) void norm_rope_kernel(
    float* __restrict__ data, const float* __restrict__ scale,
    const float* __restrict__ sinp, const float* __restrict__ cosp,
    int rowstride)
{
    const int s = blockIdx.x;
    const int h = blockIdx.y;
    const int d = threadIdx.x;           // 0..63
    float* p = data + (size_t)s * rowstride + h * HEAD_DIM;

    float v = p[d];

    // sum of squares over 64 lanes (2 warps)
    float sq = v * v;
    #pragma unroll
    for (int o = 16; o; o >>= 1) sq += __shfl_xor_sync(0xffffffffu, sq, o);
    __shared__ float ws[2];
    if ((d & 31) == 0) ws[d >> 5] = sq;
    __syncthreads();
    const float total = ws[0] + ws[1];
    const float r = rsqrtf(total * (1.0f / 64.0f) + 1e-6f);

    const float xn = v * r * scale[d];
    __shared__ float sm[64];
    sm[d] = xn;
    __syncthreads();
    const float rot = (d < 32) ? -sm[d + 32] : sm[d - 32];
    p[d] = xn * cosp[s * HEAD_DIM + d] + rot * sinp[s * HEAD_DIM + d];
}

// ---------------------------------------------------------------------------
// Causal GQA attention, one block per (query row s, head h).
// Two-pass softmax with scores in shared memory (max 2048 keys = 8 KB).
// q: [S, 2048]  k,v: [S, 512]  out: [S, 2048]
// ---------------------------------------------------------------------------
__global__ __launch_bounds__(256) void attn_kernel(
    const float* __restrict__ q, const float* __restrict__ k,
    const float* __restrict__ v, float* __restrict__ out)
{
    const int s = blockIdx.x;
    const int h = blockIdx.y;
    const int g = h >> 2;                 // kv head (GS = 4)
    const int tid = threadIdx.x;
    const int lane = tid & 31;
    const int warp = tid >> 5;            // 0..7
    const int L = s + 1;                  // causal key count

    __shared__ float sc[S_LEN];
    __shared__ float qv[HEAD_DIM];
    __shared__ float redbuf[8];
    __shared__ float pacc[4][HEAD_DIM];

    if (tid < HEAD_DIM) qv[tid] = q[(size_t)s * D_Q + h * HEAD_DIM + tid];
    __syncthreads();

    // scores: one warp per key
    const float kscale = 0.125f;  // 1/sqrt(64)
    for (int j = warp; j < L; j += 8) {
        const float* kr = k + (size_t)j * D_KV + g * HEAD_DIM;
        float dp = qv[lane] * kr[lane] + qv[lane + 32] * kr[lane + 32];
        #pragma unroll
        for (int o = 16; o; o >>= 1) dp += __shfl_xor_sync(0xffffffffu, dp, o);
        if (lane == 0) sc[j] = dp * kscale;
    }
    __syncthreads();

    // block max
    float m = -1e30f;
    for (int j = tid; j < L; j += 256) m = fmaxf(m, sc[j]);
    #pragma unroll
    for (int o = 16; o; o >>= 1) m = fmaxf(m, __shfl_xor_sync(0xffffffffu, m, o));
    if (lane == 0) redbuf[warp] = m;
    __syncthreads();
    m = redbuf[0];
    #pragma unroll
    for (int w = 1; w < 8; w++) m = fmaxf(m, redbuf[w]);
    __syncthreads();   // before redbuf reuse

    // exp + sum
    float sum = 0.0f;
    for (int j = tid; j < L; j += 256) {
        float p = expf(sc[j] - m);
        sc[j] = p;
        sum += p;
    }
    #pragma unroll
    for (int o = 16; o; o >>= 1) sum += __shfl_xor_sync(0xffffffffu, sum, o);
    if (lane == 0) redbuf[warp] = sum;
    __syncthreads();   // also makes sc[] writes visible block-wide
    float tot = 0.0f;
    #pragma unroll
    for (int w = 0; w < 8; w++) tot += redbuf[w];
    const float inv = 1.0f / tot;

    // output: 4 key-chunks x 64 dims
    const int d = tid & 63;
    const int c = tid >> 6;               // 0..3
    float acc = 0.0f;
    for (int j = c; j < L; j += 4)
        acc += sc[j] * v[(size_t)j * D_KV + g * HEAD_DIM + d];
    pacc[c][d] = acc;
    __syncthreads();
    if (tid < HEAD_DIM) {
        float o = (pacc[0][tid] + pacc[1][tid] + pacc[2][tid] + pacc[3][tid]) * inv;
        out[(size_t)s * D_Q + h * HEAD_DIM + tid] = o;
    }
}

// ---------------------------------------------------------------------------
// Launch
// inputs: 0:x 1:sin 2:cos 3:mask 4:Wq 5:Wk 6:Wv 7:Wo 8:bo 9:q_scale 10:k_scale
// ---------------------------------------------------------------------------
extern "C" void kernel_launch(void* const* d_in, const int* in_sizes, int n_in,
                              void* d_out, int out_size)
{
    const float* x       = (const float*)d_in[0];
    const float* sinp    = (const float*)d_in[1];
    const float* cosp    = (const float*)d_in[2];
    const float* Wq      = (const float*)d_in[4];
    const float* Wk      = (const float*)d_in[5];
    const float* Wv      = (const float*)d_in[6];
    const float* Wo      = (const float*)d_in[7];
    const float* bo      = (const float*)d_in[8];
    const float* q_scale = (const float*)d_in[9];
    const float* k_scale = (const float*)d_in[10];
    float* out = (float*)d_out;

    float *pq, *pk, *pv, *pao;
    cudaGetSymbolAddress((void**)&pq, g_q);
    cudaGetSymbolAddress((void**)&pk, g_k);
    cudaGetSymbolAddress((void**)&pv, g_v);
    cudaGetSymbolAddress((void**)&pao, g_ao);

    // QKV projections
    sgemm_kernel<<<dim3(D_Q / 64, S_LEN / 64), 256>>>(x, Wq, pq, nullptr, S_LEN, D_Q, D_MODEL);
    sgemm_kernel<<<dim3(D_KV / 64, S_LEN / 64), 256>>>(x, Wk, pk, nullptr, S_LEN, D_KV, D_MODEL);
    sgemm_kernel<<<dim3(D_KV / 64, S_LEN / 64), 256>>>(x, Wv, pv, nullptr, S_LEN, D_KV, D_MODEL);

    // RMSNorm + RoPE (in place)
    norm_rope_kernel<<<dim3(S_LEN, HEADS), 64>>>(pq, q_scale, sinp, cosp, D_Q);
    norm_rope_kernel<<<dim3(S_LEN, NKV), 64>>>(pk, k_scale, sinp, cosp, D_KV);

    // Causal GQA attention
    attn_kernel<<<dim3(S_LEN, HEADS), 256>>>(pq, pk, pv, pao);

    // Output projection + bias
    sgemm_kernel<<<dim3(D_MODEL / 64, S_LEN / 64), 256>>>(pao, Wo, out, bo, S_LEN, D_MODEL, D_Q);
}